// round 16
// baseline (speedup 1.0000x reference)
#include <cuda_runtime.h>
#include <cuda_fp16.h>
#include <math.h>
#include <stdint.h>

// ---------------- problem dims (fixed) ----------------------------------------
#define BATCH 16384
#define DIN   2048
#define HEADS 16
#define DHEAD 128
#define DOUT  512
#define NQKV  (3 * DIN)                 // 6144

// ---------------- scratch (static device memory) ------------------------------
__device__ __half g_xh  [BATCH * DIN];
__device__ __half g_qkvh[(size_t)BATCH * NQKV];
__device__ __half g_att [BATCH * DIN];
__device__ __half g_opr [BATCH * DIN];
__device__ __half g_gt  [BATCH * DIN];
__device__ __half g_kvT [HEADS * DHEAD * DHEAD];  // kv transposed [h][e][d], half
__device__ float  g_ksum[HEADS * DHEAD];
#define KV_SPLIT 32
__device__ float g_kvpart[KV_SPLIT * HEADS * DHEAD * DHEAD];   // [chunk][h][e][d]
__device__ float g_ksumpart[KV_SPLIT * DIN];
// transposed half weights [N][K]
__device__ __half g_wqkvT[NQKV * DIN];
__device__ __half g_woT  [DIN * DIN];
__device__ __half g_wgT  [DIN * 2 * DIN];
__device__ __half g_woutT[DOUT * DIN];

// ---------------- helpers -------------------------------------------------------
__device__ __forceinline__ uint32_t smem_u32(const void* p) {
    uint32_t a;
    asm("{ .reg .u64 t; cvta.to.shared.u64 t, %1; cvt.u32.u64 %0, t; }" : "=r"(a) : "l"(p));
    return a;
}
__device__ __forceinline__ void cp16(uint32_t dst, const void* src) {
    asm volatile("cp.async.cg.shared.global [%0], [%1], 16;" :: "r"(dst), "l"(src));
}
#define CP_COMMIT() asm volatile("cp.async.commit_group;" ::: "memory")
#define CP_WAIT(n)  asm volatile("cp.async.wait_group %0;" :: "n"(n) : "memory")

#define MMA_F16(d, A4, B2) \
    asm volatile("mma.sync.aligned.m16n8k16.row.col.f32.f16.f16.f32 " \
        "{%0,%1,%2,%3},{%4,%5,%6,%7},{%8,%9},{%0,%1,%2,%3};" \
        : "+f"((d)[0]), "+f"((d)[1]), "+f"((d)[2]), "+f"((d)[3]) \
        : "r"((A4)[0]), "r"((A4)[1]), "r"((A4)[2]), "r"((A4)[3]), \
          "r"((B2)[0]), "r"((B2)[1]))

#define LDSM_X4(r0, r1, r2, r3, addr) \
    asm volatile("ldmatrix.sync.aligned.m8n8.x4.shared.b16 {%0,%1,%2,%3}, [%4];" \
        : "=r"(r0), "=r"(r1), "=r"(r2), "=r"(r3) : "r"(addr))

#define LDSM_X4_T(r0, r1, r2, r3, addr) \
    asm volatile("ldmatrix.sync.aligned.m8n8.x4.trans.shared.b16 {%0,%1,%2,%3}, [%4];" \
        : "=r"(r0), "=r"(r1), "=r"(r2), "=r"(r3) : "r"(addr))

// ---------------- GEMM config (R13 best: 256 thr, BK=64, 2 CTAs/SM) --------------
#define BM 128
#define BN 128
#define BK 64
#define STAGES 3
#define ARS 72
#define BRS 72
#define ASTGH (BM * ARS)
#define BSTGH (BN * BRS)
#define GEMM_SMEM (STAGES * (ASTGH + BSTGH) * 2)   // 110592 bytes

// MODE 2: C=acc+bias (fp32 out)
// MODE 3: g=sigmoid(acc+bias); Ch=half(g*hep+(1-g)*hex)
// MODE 4: Ch=half(acc+bias)
// MODE 5: QKV fused: col<2*DIN -> relu(acc)+1e-4, else acc; Ch=half
template <int MODE>
__global__ void __launch_bounds__(256, 2) gemm_h(
    const __half* __restrict__ A0, const __half* __restrict__ A1, int K0, int nkt,
    const __half* __restrict__ B, int ldb,
    const float* __restrict__ bias,
    const __half* __restrict__ hep, const __half* __restrict__ hex,
    float* __restrict__ C, __half* __restrict__ Ch, int N)
{
    extern __shared__ __half smh[];
    __half* As = smh;
    __half* Bs = smh + STAGES * ASTGH;
    const uint32_t asu = smem_u32(As);
    const uint32_t bsu = smem_u32(Bs);

    const int tid  = threadIdx.x;
    const int bm   = blockIdx.y * BM;
    const int bn   = blockIdx.x * BN;
    const int wid  = tid >> 5, lane = tid & 31;
    const int wm   = (wid >> 2) * 64;
    const int wn   = (wid & 3) * 32;

    const uint32_t a_lane = (uint32_t)(((lane & 15) * ARS + (lane >> 4) * 8) * 2);
    const uint32_t b_lane = (uint32_t)(((((lane >> 4) << 3) + (lane & 7)) * BRS
                                        + ((lane >> 3) & 1) * 8) * 2);

    float acc[4][4][4];
#pragma unroll
    for (int mt = 0; mt < 4; mt++)
#pragma unroll
        for (int nt = 0; nt < 4; nt++)
#pragma unroll
            for (int e = 0; e < 4; e++) acc[mt][nt][e] = 0.0f;

    auto issue = [&](int kt) {
        const int s = kt % STAGES;
        const int kbase = kt * BK;
        const __half* Aptr;
        int kc;
        if (kbase < K0) { Aptr = A0; kc = kbase; }
        else            { Aptr = A1; kc = kbase - K0; }
#pragma unroll
        for (int i = 0; i < 4; i++) {
            int idx = tid + i * 256;
            int r = idx >> 3, g = idx & 7;
            uint32_t dst = asu + (uint32_t)(s * ASTGH + r * ARS + g * 8) * 2u;
            cp16(dst, Aptr + (size_t)(bm + r) * DIN + kc + g * 8);
        }
#pragma unroll
        for (int i = 0; i < 4; i++) {
            int idx = tid + i * 256;
            int r = idx >> 3, g = idx & 7;
            uint32_t dst = bsu + (uint32_t)(s * BSTGH + r * BRS + g * 8) * 2u;
            cp16(dst, B + (size_t)(bn + r) * ldb + kbase + g * 8);
        }
    };

#pragma unroll
    for (int kt = 0; kt < STAGES - 1; kt++) {
        if (kt < nkt) issue(kt);
        CP_COMMIT();
    }

    for (int kt = 0; kt < nkt; kt++) {
        CP_WAIT(STAGES - 2);
        __syncthreads();

        if (kt + STAGES - 1 < nkt) issue(kt + STAGES - 1);
        CP_COMMIT();

        const int s = kt % STAGES;
        const uint32_t abase = asu + (uint32_t)(s * ASTGH + wm * ARS) * 2u + a_lane;
        const uint32_t bbase = bsu + (uint32_t)(s * BSTGH + wn * BRS) * 2u + b_lane;

        uint32_t a[2][4][4], b[2][4][2];
#pragma unroll
        for (int mt = 0; mt < 4; mt++)
            LDSM_X4(a[0][mt][0], a[0][mt][1], a[0][mt][2], a[0][mt][3],
                    abase + (uint32_t)(mt * 16 * ARS * 2));
#pragma unroll
        for (int p = 0; p < 2; p++)
            LDSM_X4(b[0][2 * p][0], b[0][2 * p][1], b[0][2 * p + 1][0], b[0][2 * p + 1][1],
                    bbase + (uint32_t)(p * 16 * BRS * 2));

#pragma unroll
        for (int kc = 0; kc < 4; kc++) {
            const int cur = kc & 1, nxt = cur ^ 1;
            if (kc < 3) {
                const uint32_t ko = (uint32_t)((kc + 1) * 32);
#pragma unroll
                for (int mt = 0; mt < 4; mt++)
                    LDSM_X4(a[nxt][mt][0], a[nxt][mt][1], a[nxt][mt][2], a[nxt][mt][3],
                            abase + (uint32_t)(mt * 16 * ARS * 2) + ko);
#pragma unroll
                for (int p = 0; p < 2; p++)
                    LDSM_X4(b[nxt][2 * p][0], b[nxt][2 * p][1],
                            b[nxt][2 * p + 1][0], b[nxt][2 * p + 1][1],
                            bbase + (uint32_t)(p * 16 * BRS * 2) + ko);
            }
#pragma unroll
            for (int mt = 0; mt < 4; mt++)
#pragma unroll
                for (int nt = 0; nt < 4; nt++)
                    MMA_F16(acc[mt][nt], a[cur][mt], b[cur][nt]);
        }
    }

    // ---- epilogue ----
    const int lr = lane >> 2, lc = lane & 3;
#pragma unroll
    for (int mt = 0; mt < 4; mt++) {
#pragma unroll
        for (int nt = 0; nt < 4; nt++) {
#pragma unroll
            for (int h = 0; h < 2; h++) {
                const int gr = bm + wm + mt * 16 + lr + h * 8;
                const int gc = bn + wn + nt * 8 + 2 * lc;
                const size_t gi = (size_t)gr * N + gc;
                float v0 = acc[mt][nt][h * 2 + 0];
                float v1 = acc[mt][nt][h * 2 + 1];
                if constexpr (MODE == 2) {
                    v0 += bias[gc]; v1 += bias[gc + 1];
                    *(float2*)&C[gi] = make_float2(v0, v1);
                } else if constexpr (MODE == 3) {
                    v0 += bias[gc]; v1 += bias[gc + 1];
                    const float g0 = 1.f / (1.f + expf(-v0));
                    const float g1 = 1.f / (1.f + expf(-v1));
                    const float2 e2 = __half22float2(*(const __half2*)&hep[gi]);
                    const float2 x2 = __half22float2(*(const __half2*)&hex[gi]);
                    const float r0 = g0 * e2.x + (1.f - g0) * x2.x;
                    const float r1 = g1 * e2.y + (1.f - g1) * x2.y;
                    *(__half2*)&Ch[gi] = __floats2half2_rn(r0, r1);
                } else if constexpr (MODE == 4) {
                    v0 += bias[gc]; v1 += bias[gc + 1];
                    *(__half2*)&Ch[gi] = __floats2half2_rn(v0, v1);
                } else {  // MODE 5
                    if (gc < 2 * DIN) {
                        v0 = fmaxf(v0, 0.f) + 1e-4f;
                        v1 = fmaxf(v1, 0.f) + 1e-4f;
                    }
                    *(__half2*)&Ch[gi] = __floats2half2_rn(v0, v1);
                }
            }
        }
    }
}

// ---------------- fp32 -> half copy ----------------------------------------------
__global__ void half_copy(const float4* __restrict__ s, __half2* __restrict__ d)
{
    const int i = blockIdx.x * 256 + threadIdx.x;
    float4 v = s[i];
    d[2 * i]     = __floats2half2_rn(v.x, v.y);
    d[2 * i + 1] = __floats2half2_rn(v.z, v.w);
}

// ---------------- transpose + convert: WT[n][k] = half(W[k][n]) -------------------
__global__ void transpose_half(const float* __restrict__ S, __half* __restrict__ D,
                               int K, int N)
{
    __shared__ float t[32][33];
    const int bn = blockIdx.x * 32, bk = blockIdx.y * 32;
    const int tx = threadIdx.x, ty = threadIdx.y;
#pragma unroll
    for (int i = 0; i < 32; i += 8)
        t[ty + i][tx] = S[(size_t)(bk + ty + i) * N + bn + tx];
    __syncthreads();
#pragma unroll
    for (int i = 0; i < 32; i += 8)
        D[(size_t)(bn + ty + i) * K + bk + tx] = __float2half_rn(t[tx][ty + i]);
}

// fused 3-way transpose for Wq/Wk/Wv
__global__ void transpose_qkv(const float* __restrict__ Wq, const float* __restrict__ Wk,
                              const float* __restrict__ Wv, __half* __restrict__ D)
{
    __shared__ float t[32][33];
    const float* S = (blockIdx.z == 0) ? Wq : (blockIdx.z == 1) ? Wk : Wv;
    __half* Dz = D + (size_t)blockIdx.z * DIN * DIN;
    const int bn = blockIdx.x * 32, bk = blockIdx.y * 32;
    const int tx = threadIdx.x, ty = threadIdx.y;
#pragma unroll
    for (int i = 0; i < 32; i += 8)
        t[ty + i][tx] = S[(size_t)(bk + ty + i) * DIN + bn + tx];
    __syncthreads();
#pragma unroll
    for (int i = 0; i < 32; i += 8)
        Dz[(size_t)(bn + ty + i) * DIN + bk + tx] = __float2half_rn(t[tx][ty + i]);
}

// ---------------- kv via HMMA: kvpart[chunk][h][e][d] = sum_b v[b][e]*k[b][d] ------
#define KVRS 136
__global__ void __launch_bounds__(256) kv_mma(const __half* __restrict__ qkv)
{
    __shared__ __half ksm[2][16 * KVRS];
    __shared__ __half vsm[2][16 * KVRS];
    __shared__ float ksum_s[256];

    const int h = blockIdx.x;
    const int chunk = blockIdx.y;
    const int b0 = chunk * (BATCH / KV_SPLIT);   // 512 rows
    const int tid = threadIdx.x;
    const int wid = tid >> 5, lane = tid & 31;
    const int wm = (wid >> 2) * 64;
    const int wn = (wid & 3) * 32;

    const __half* kbase = qkv + 2048 + h * DHEAD;
    const __half* vbase = qkv + 4096 + h * DHEAD;
    const uint32_t ksu = smem_u32(&ksm[0][0]);
    const uint32_t vsu = smem_u32(&vsm[0][0]);

    const uint32_t a_lane = (uint32_t)((((lane & 7) + ((lane >> 4) & 1) * 8) * KVRS
                                        + ((lane >> 3) & 1) * 8) * 2);
    const uint32_t b_lane = (uint32_t)((((lane & 7) + ((lane >> 3) & 1) * 8) * KVRS
                                        + ((lane >> 4) & 1) * 8) * 2);

    auto load = [&](int buf, int bb) {
        const int r = tid >> 4, g = tid & 15;
        const size_t row = (size_t)(b0 + bb + r) * NQKV;
        cp16(ksu + (uint32_t)(buf * 16 * KVRS + r * KVRS + g * 8) * 2u, kbase + row + g * 8);
        cp16(vsu + (uint32_t)(buf * 16 * KVRS + r * KVRS + g * 8) * 2u, vbase + row + g * 8);
    };

    float acc[4][4][4];
#pragma unroll
    for (int mt = 0; mt < 4; mt++)
#pragma unroll
        for (int nt = 0; nt < 4; nt++)
#pragma unroll
            for (int e = 0; e < 4; e++) acc[mt][nt][e] = 0.0f;
    float ksacc = 0.0f;
    const int kcol = tid & 127;
    const int krb  = (tid >> 7) * 8;

    load(0, 0);
    CP_COMMIT();

    for (int it = 0; it < (BATCH / KV_SPLIT) / 16; it++) {   // 32 iters
        const int buf = it & 1;
        if (it + 1 < (BATCH / KV_SPLIT) / 16) load(buf ^ 1, (it + 1) * 16);
        CP_COMMIT();
        CP_WAIT(1);
        __syncthreads();

        const uint32_t kb = ksu + (uint32_t)(buf * 16 * KVRS) * 2u;
        const uint32_t vb = vsu + (uint32_t)(buf * 16 * KVRS) * 2u;

        uint32_t a[4][4], b[4][2];
#pragma unroll
        for (int mt = 0; mt < 4; mt++)
            LDSM_X4_T(a[mt][0], a[mt][1], a[mt][2], a[mt][3],
                      vb + a_lane + (uint32_t)((wm + mt * 16) * 2));
#pragma unroll
        for (int p = 0; p < 2; p++)
            LDSM_X4_T(b[2 * p][0], b[2 * p][1], b[2 * p + 1][0], b[2 * p + 1][1],
                      kb + b_lane + (uint32_t)((wn + p * 16) * 2));
#pragma unroll
        for (int mt = 0; mt < 4; mt++)
#pragma unroll
            for (int nt = 0; nt < 4; nt++)
                MMA_F16(acc[mt][nt], a[mt], b[nt]);

        const __half* kcolp = &ksm[buf][krb * KVRS + kcol];
#pragma unroll
        for (int r = 0; r < 8; r++) ksacc += __half2float(kcolp[r * KVRS]);
        __syncthreads();
    }

    float* dst = g_kvpart + (size_t)chunk * (HEADS * DHEAD * DHEAD) + h * DHEAD * DHEAD;
    const int lr = lane >> 2, lc = lane & 3;
#pragma unroll
    for (int mt = 0; mt < 4; mt++)
#pragma unroll
        for (int nt = 0; nt < 4; nt++)
#pragma unroll
            for (int hh = 0; hh < 2; hh++) {
                const int e = wm + mt * 16 + lr + hh * 8;
                const int d = wn + nt * 8 + 2 * lc;
                *(float2*)&dst[e * DHEAD + d] =
                    make_float2(acc[mt][nt][hh * 2 + 0], acc[mt][nt][hh * 2 + 1]);
            }

    ksum_s[tid] = ksacc;
    __syncthreads();
    if (tid < 128)
        g_ksumpart[chunk * DIN + h * DHEAD + tid] = ksum_s[tid] + ksum_s[tid + 128];
}

// ---------------- final reductions (vectorized): kvT (half) + ksum (fp32) ----------
__global__ void kv_final()
{
    const int i4 = blockIdx.x * 256 + threadIdx.x;     // handles 4 consecutive floats
    float4 s = make_float4(0.f, 0.f, 0.f, 0.f);
    for (int c = 0; c < KV_SPLIT; c++) {
        const float4 p = *(const float4*)&g_kvpart[(size_t)c * (HEADS * DHEAD * DHEAD) + i4 * 4];
        s.x += p.x; s.y += p.y; s.z += p.z; s.w += p.w;
    }
    *(__half2*)&g_kvT[i4 * 4]     = __floats2half2_rn(s.x, s.y);
    *(__half2*)&g_kvT[i4 * 4 + 2] = __floats2half2_rn(s.z, s.w);

    if (i4 < DIN / 4) {
        float4 t = make_float4(0.f, 0.f, 0.f, 0.f);
        for (int c = 0; c < KV_SPLIT; c++) {
            const float4 p = *(const float4*)&g_ksumpart[c * DIN + i4 * 4];
            t.x += p.x; t.y += p.y; t.z += p.z; t.w += p.w;
        }
        *(float4*)&g_ksum[i4 * 4] = t;
    }
}

// ---------------- attention via HMMA: att = (q @ kvT^T) * z ------------------------
#define ATT_SMEM (2 * 128 * 72 * 2 * 2 + 1024)
__global__ void __launch_bounds__(256) attn_mma(const __half* __restrict__ qkv,
                                                __half* __restrict__ att)
{
    extern __shared__ char smc[];
    __half* As = (__half*)smc;
    __half* Bs = (__half*)(smc + 2 * 128 * 72 * 2);
    float* ksum_s = (float*)(smc + 4 * 128 * 72 * 2);
    float* z_s    = ksum_s + 128;

    const int h  = blockIdx.y;
    const int b0 = blockIdx.x * 128;
    const int tid = threadIdx.x;
    const int wid = tid >> 5, lane = tid & 31;
    const int wm = (wid >> 2) * 64, wn = (wid & 3) * 32;
    const uint32_t asu = smem_u32(As), bsu = smem_u32(Bs);

    const __half* qb  = qkv + h * DHEAD;
    const __half* kvb = g_kvT + (size_t)h * DHEAD * DHEAD;

#pragma unroll
    for (int kt = 0; kt < 2; kt++) {
#pragma unroll
        for (int i = 0; i < 4; i++) {
            int idx = tid + i * 256;
            int r = idx >> 3, g = idx & 7;
            cp16(asu + (uint32_t)(kt * 128 * 72 + r * 72 + g * 8) * 2u,
                 qb + (size_t)(b0 + r) * NQKV + kt * 64 + g * 8);
            cp16(bsu + (uint32_t)(kt * 128 * 72 + r * 72 + g * 8) * 2u,
                 kvb + r * DHEAD + kt * 64 + g * 8);
        }
    }
    CP_COMMIT();
    if (tid < 128) ksum_s[tid] = g_ksum[h * DHEAD + tid];
    CP_WAIT(0);
    __syncthreads();

    {
        int r = tid >> 1, hf = tid & 1;
        const __half* qrow = As + hf * 128 * 72 + r * 72;
        float s = 0.0f;
        for (int d = 0; d < 64; d++) s += __half2float(qrow[d]) * ksum_s[hf * 64 + d];
        s += __shfl_xor_sync(0xffffffffu, s, 1);
        if (hf == 0) z_s[r] = 1.0f / (s + 1e-6f);
    }
    __syncthreads();

    const uint32_t a_lane = (uint32_t)(((lane & 15) * 72 + (lane >> 4) * 8) * 2);
    const uint32_t b_lane = (uint32_t)(((((lane >> 4) << 3) + (lane & 7)) * 72
                                        + ((lane >> 3) & 1) * 8) * 2);

    float acc[4][4][4];
#pragma unroll
    for (int mt = 0; mt < 4; mt++)
#pragma unroll
        for (int nt = 0; nt < 4; nt++)
#pragma unroll
            for (int e = 0; e < 4; e++) acc[mt][nt][e] = 0.0f;

#pragma unroll
    for (int kt = 0; kt < 2; kt++) {
        const uint32_t abase = asu + (uint32_t)(kt * 128 * 72 + wm * 72) * 2u + a_lane;
        const uint32_t bbase = bsu + (uint32_t)(kt * 128 * 72 + wn * 72) * 2u + b_lane;
#pragma unroll
        for (int kc = 0; kc < 4; kc++) {
            uint32_t a[4][4], b[4][2];
            const uint32_t ko = (uint32_t)(kc * 32);
#pragma unroll
            for (int mt = 0; mt < 4; mt++)
                LDSM_X4(a[mt][0], a[mt][1], a[mt][2], a[mt][3],
                        abase + (uint32_t)(mt * 16 * 72 * 2) + ko);
#pragma unroll
            for (int p = 0; p < 2; p++)
                LDSM_X4(b[2 * p][0], b[2 * p][1], b[2 * p + 1][0], b[2 * p + 1][1],
                        bbase + (uint32_t)(p * 16 * 72 * 2) + ko);
#pragma unroll
            for (int mt = 0; mt < 4; mt++)
#pragma unroll
                for (int nt = 0; nt < 4; nt++)
                    MMA_F16(acc[mt][nt], a[mt], b[nt]);
        }
    }

    const int lr = lane >> 2, lc = lane & 3;
#pragma unroll
    for (int mt = 0; mt < 4; mt++) {
#pragma unroll
        for (int nt = 0; nt < 4; nt++) {
#pragma unroll
            for (int hh = 0; hh < 2; hh++) {
                const int rl = wm + mt * 16 + lr + hh * 8;
                const int gc = wn + nt * 8 + 2 * lc;
                const float z = z_s[rl];
                const float v0 = acc[mt][nt][hh * 2 + 0] * z;
                const float v1 = acc[mt][nt][hh * 2 + 1] * z;
                *(__half2*)&att[(size_t)(b0 + rl) * DIN + h * DHEAD + gc] =
                    __floats2half2_rn(v0, v1);
            }
        }
    }
}

// ---------------- launch -----------------------------------------------------------
extern "C" void kernel_launch(void* const* d_in, const int* in_sizes, int n_in,
                              void* d_out, int out_size)
{
    const float* x    = (const float*)d_in[0];
    const float* Wq   = (const float*)d_in[1];
    const float* Wk   = (const float*)d_in[2];
    const float* Wv   = (const float*)d_in[3];
    const float* Wo   = (const float*)d_in[4];
    const float* bo   = (const float*)d_in[5];
    const float* Wg   = (const float*)d_in[6];
    const float* bg   = (const float*)d_in[7];
    const float* Wout = (const float*)d_in[8];
    const float* bout = (const float*)d_in[9];
    float* out = (float*)d_out;

    __half *xh_, *qkvh_, *att_, *opr_, *gt_;
    __half *wqkvT_, *woT_, *wgT_, *woutT_;
    cudaGetSymbolAddress((void**)&xh_,    g_xh);
    cudaGetSymbolAddress((void**)&qkvh_,  g_qkvh);
    cudaGetSymbolAddress((void**)&att_,   g_att);
    cudaGetSymbolAddress((void**)&opr_,   g_opr);
    cudaGetSymbolAddress((void**)&gt_,    g_gt);
    cudaGetSymbolAddress((void**)&wqkvT_, g_wqkvT);
    cudaGetSymbolAddress((void**)&woT_,   g_woT);
    cudaGetSymbolAddress((void**)&wgT_,   g_wgT);
    cudaGetSymbolAddress((void**)&woutT_, g_woutT);

    cudaFuncSetAttribute(gemm_h<2>, cudaFuncAttributeMaxDynamicSharedMemorySize, GEMM_SMEM);
    cudaFuncSetAttribute(gemm_h<3>, cudaFuncAttributeMaxDynamicSharedMemorySize, GEMM_SMEM);
    cudaFuncSetAttribute(gemm_h<4>, cudaFuncAttributeMaxDynamicSharedMemorySize, GEMM_SMEM);
    cudaFuncSetAttribute(gemm_h<5>, cudaFuncAttributeMaxDynamicSharedMemorySize, GEMM_SMEM);
    cudaFuncSetAttribute(attn_mma, cudaFuncAttributeMaxDynamicSharedMemorySize, ATT_SMEM);

    const dim3 blk(256);
    const dim3 tblk(32, 8);

    // idx 0-2: prep; idx 3 = QKV GEMM (ncu lands here)
    half_copy<<<(BATCH * DIN) / 1024, 256>>>((const float4*)x, (__half2*)xh_);        // 0
    transpose_qkv<<<dim3(DIN / 32, DIN / 32, 3), tblk>>>(Wq, Wk, Wv, wqkvT_);         // 1
    transpose_half<<<dim3(DIN / 32, DIN / 32), tblk>>>(Wo, woT_, DIN, DIN);           // 2

    // 3: fused QKV GEMM -> half qkv, relu-feature on q,k columns
    gemm_h<5><<<dim3(NQKV / BN, BATCH / BM), blk, GEMM_SMEM>>>(
        xh_, xh_, DIN, DIN / BK, wqkvT_, DIN,
        nullptr, nullptr, nullptr, nullptr, qkvh_, NQKV);

    transpose_half<<<dim3(DIN / 32, (2 * DIN) / 32), tblk>>>(Wg, wgT_, 2 * DIN, DIN); // 4
    transpose_half<<<dim3(DOUT / 32, DIN / 32), tblk>>>(Wout, woutT_, DIN, DOUT);     // 5

    // kv + ksum partials via HMMA, then vectorized final reduce
    kv_mma<<<dim3(HEADS, KV_SPLIT), 256>>>(qkvh_);
    kv_final<<<dim3((HEADS * DHEAD * DHEAD) / 1024), 256>>>();

    // attention via HMMA
    attn_mma<<<dim3(BATCH / 128, HEADS), 256, ATT_SMEM>>>(qkvh_, att_);

    // out_proj = att @ Wo + bo -> half opr
    gemm_h<4><<<dim3(DIN / BN, BATCH / BM), blk, GEMM_SMEM>>>(
        att_, att_, DIN, DIN / BK, woT_, DIN,
        bo, nullptr, nullptr, nullptr, opr_, DIN);

    // gate GEMM over concat [opr | xh]; blend half opr / xh -> half gt
    gemm_h<3><<<dim3(DIN / BN, BATCH / BM), blk, GEMM_SMEM>>>(
        opr_, xh_, DIN, (2 * DIN) / BK, wgT_, 2 * DIN,
        bg, opr_, xh_, nullptr, gt_, DIN);

    // out = gt @ Wout + bout (fp32)
    gemm_h<2><<<dim3(DOUT / BN, BATCH / BM), blk, GEMM_SMEM>>>(
        gt_, gt_, DIN, DIN / BK, woutT_, DIN,
        bout, nullptr, nullptr, out, nullptr, DOUT);
}

// round 17
// speedup vs baseline: 1.0144x; 1.0144x over previous
#include <cuda_runtime.h>
#include <cuda_fp16.h>
#include <math.h>
#include <stdint.h>

// ---------------- problem dims (fixed) ----------------------------------------
#define BATCH 16384
#define DIN   2048
#define HEADS 16
#define DHEAD 128
#define DOUT  512
#define NQKV  (3 * DIN)                 // 6144

// ---------------- scratch (static device memory) ------------------------------
__device__ __half g_xh  [BATCH * DIN];
__device__ __half g_qkvh[(size_t)BATCH * NQKV];
__device__ __half g_att [BATCH * DIN];
__device__ __half g_opr [BATCH * DIN];
__device__ __half g_gt  [BATCH * DIN];
__device__ __half g_kvT [HEADS * DHEAD * DHEAD];  // kv transposed [h][e][d], half
__device__ float  g_ksum[HEADS * DHEAD];
#define KV_SPLIT 32
__device__ float g_kvpart[KV_SPLIT * HEADS * DHEAD * DHEAD];   // [chunk][h][e][d]
__device__ float g_ksumpart[KV_SPLIT * DIN];
// transposed half weights [N][K]
__device__ __half g_wqkvT[NQKV * DIN];
__device__ __half g_woT  [DIN * DIN];
__device__ __half g_wgT  [DIN * 2 * DIN];
__device__ __half g_woutT[DOUT * DIN];

// ---------------- helpers -------------------------------------------------------
__device__ __forceinline__ uint32_t smem_u32(const void* p) {
    uint32_t a;
    asm("{ .reg .u64 t; cvta.to.shared.u64 t, %1; cvt.u32.u64 %0, t; }" : "=r"(a) : "l"(p));
    return a;
}
__device__ __forceinline__ void cp16(uint32_t dst, const void* src) {
    asm volatile("cp.async.cg.shared.global [%0], [%1], 16;" :: "r"(dst), "l"(src));
}
#define CP_COMMIT() asm volatile("cp.async.commit_group;" ::: "memory")
#define CP_WAIT(n)  asm volatile("cp.async.wait_group %0;" :: "n"(n) : "memory")

#define MMA_F16(d, A4, B2) \
    asm volatile("mma.sync.aligned.m16n8k16.row.col.f32.f16.f16.f32 " \
        "{%0,%1,%2,%3},{%4,%5,%6,%7},{%8,%9},{%0,%1,%2,%3};" \
        : "+f"((d)[0]), "+f"((d)[1]), "+f"((d)[2]), "+f"((d)[3]) \
        : "r"((A4)[0]), "r"((A4)[1]), "r"((A4)[2]), "r"((A4)[3]), \
          "r"((B2)[0]), "r"((B2)[1]))

#define LDSM_X4(r0, r1, r2, r3, addr) \
    asm volatile("ldmatrix.sync.aligned.m8n8.x4.shared.b16 {%0,%1,%2,%3}, [%4];" \
        : "=r"(r0), "=r"(r1), "=r"(r2), "=r"(r3) : "r"(addr))

#define LDSM_X4_T(r0, r1, r2, r3, addr) \
    asm volatile("ldmatrix.sync.aligned.m8n8.x4.trans.shared.b16 {%0,%1,%2,%3}, [%4];" \
        : "=r"(r0), "=r"(r1), "=r"(r2), "=r"(r3) : "r"(addr))

// ---------------- GEMM config (best: 256 thr, BK=64, 2 CTAs/SM) -------------------
#define BM 128
#define BN 128
#define BK 64
#define STAGES 3
#define ARS 72
#define BRS 72
#define ASTGH (BM * ARS)
#define BSTGH (BN * BRS)
#define GEMM_SMEM (STAGES * (ASTGH + BSTGH) * 2)   // 110592 bytes

// MODE 2: C=acc+bias (fp32 out)
// MODE 3: g=sigmoid(acc+bias); Ch=half(g*hep+(1-g)*hex)
// MODE 4: Ch=half(acc+bias)
// MODE 5: QKV fused: col<2*DIN -> relu(acc)+1e-4, else acc; Ch=half
template <int MODE>
__global__ void __launch_bounds__(256, 2) gemm_h(
    const __half* __restrict__ A0, const __half* __restrict__ A1, int K0, int nkt,
    const __half* __restrict__ B, int ldb,
    const float* __restrict__ bias,
    const __half* __restrict__ hep, const __half* __restrict__ hex,
    float* __restrict__ C, __half* __restrict__ Ch, int N)
{
    extern __shared__ __half smh[];
    __half* As = smh;
    __half* Bs = smh + STAGES * ASTGH;
    const uint32_t asu = smem_u32(As);
    const uint32_t bsu = smem_u32(Bs);

    const int tid  = threadIdx.x;
    const int bm   = blockIdx.y * BM;
    const int bn   = blockIdx.x * BN;
    const int wid  = tid >> 5, lane = tid & 31;
    const int wm   = (wid >> 2) * 64;
    const int wn   = (wid & 3) * 32;

    const uint32_t a_lane = (uint32_t)(((lane & 15) * ARS + (lane >> 4) * 8) * 2);
    const uint32_t b_lane = (uint32_t)(((((lane >> 4) << 3) + (lane & 7)) * BRS
                                        + ((lane >> 3) & 1) * 8) * 2);

    float acc[4][4][4];
#pragma unroll
    for (int mt = 0; mt < 4; mt++)
#pragma unroll
        for (int nt = 0; nt < 4; nt++)
#pragma unroll
            for (int e = 0; e < 4; e++) acc[mt][nt][e] = 0.0f;

    auto issue = [&](int kt) {
        const int s = kt % STAGES;
        const int kbase = kt * BK;
        const __half* Aptr;
        int kc;
        if (kbase < K0) { Aptr = A0; kc = kbase; }
        else            { Aptr = A1; kc = kbase - K0; }
#pragma unroll
        for (int i = 0; i < 4; i++) {
            int idx = tid + i * 256;
            int r = idx >> 3, g = idx & 7;
            uint32_t dst = asu + (uint32_t)(s * ASTGH + r * ARS + g * 8) * 2u;
            cp16(dst, Aptr + (size_t)(bm + r) * DIN + kc + g * 8);
        }
#pragma unroll
        for (int i = 0; i < 4; i++) {
            int idx = tid + i * 256;
            int r = idx >> 3, g = idx & 7;
            uint32_t dst = bsu + (uint32_t)(s * BSTGH + r * BRS + g * 8) * 2u;
            cp16(dst, B + (size_t)(bn + r) * ldb + kbase + g * 8);
        }
    };

#pragma unroll
    for (int kt = 0; kt < STAGES - 1; kt++) {
        if (kt < nkt) issue(kt);
        CP_COMMIT();
    }

    for (int kt = 0; kt < nkt; kt++) {
        CP_WAIT(STAGES - 2);
        __syncthreads();

        const int s = kt % STAGES;
        const uint32_t abase = asu + (uint32_t)(s * ASTGH + wm * ARS) * 2u + a_lane;
        const uint32_t bbase = bsu + (uint32_t)(s * BSTGH + wn * BRS) * 2u + b_lane;

        uint32_t a[2][4][4], b[2][4][2];
        // critical-path kc=0 fragment preloads FIRST (next-tile cp.async has slack)
#pragma unroll
        for (int mt = 0; mt < 4; mt++)
            LDSM_X4(a[0][mt][0], a[0][mt][1], a[0][mt][2], a[0][mt][3],
                    abase + (uint32_t)(mt * 16 * ARS * 2));
#pragma unroll
        for (int p = 0; p < 2; p++)
            LDSM_X4(b[0][2 * p][0], b[0][2 * p][1], b[0][2 * p + 1][0], b[0][2 * p + 1][1],
                    bbase + (uint32_t)(p * 16 * BRS * 2));

        if (kt + STAGES - 1 < nkt) issue(kt + STAGES - 1);
        CP_COMMIT();

#pragma unroll
        for (int kc = 0; kc < 4; kc++) {
            const int cur = kc & 1, nxt = cur ^ 1;
            if (kc < 3) {
                const uint32_t ko = (uint32_t)((kc + 1) * 32);
#pragma unroll
                for (int mt = 0; mt < 4; mt++)
                    LDSM_X4(a[nxt][mt][0], a[nxt][mt][1], a[nxt][mt][2], a[nxt][mt][3],
                            abase + (uint32_t)(mt * 16 * ARS * 2) + ko);
#pragma unroll
                for (int p = 0; p < 2; p++)
                    LDSM_X4(b[nxt][2 * p][0], b[nxt][2 * p][1],
                            b[nxt][2 * p + 1][0], b[nxt][2 * p + 1][1],
                            bbase + (uint32_t)(p * 16 * BRS * 2) + ko);
            }
#pragma unroll
            for (int mt = 0; mt < 4; mt++)
#pragma unroll
                for (int nt = 0; nt < 4; nt++)
                    MMA_F16(acc[mt][nt], a[cur][mt], b[cur][nt]);
        }
    }

    // ---- epilogue ----
    const int lr = lane >> 2, lc = lane & 3;
#pragma unroll
    for (int mt = 0; mt < 4; mt++) {
#pragma unroll
        for (int nt = 0; nt < 4; nt++) {
#pragma unroll
            for (int h = 0; h < 2; h++) {
                const int gr = bm + wm + mt * 16 + lr + h * 8;
                const int gc = bn + wn + nt * 8 + 2 * lc;
                const size_t gi = (size_t)gr * N + gc;
                float v0 = acc[mt][nt][h * 2 + 0];
                float v1 = acc[mt][nt][h * 2 + 1];
                if constexpr (MODE == 2) {
                    v0 += bias[gc]; v1 += bias[gc + 1];
                    *(float2*)&C[gi] = make_float2(v0, v1);
                } else if constexpr (MODE == 3) {
                    v0 += bias[gc]; v1 += bias[gc + 1];
                    const float g0 = 1.f / (1.f + expf(-v0));
                    const float g1 = 1.f / (1.f + expf(-v1));
                    const float2 e2 = __half22float2(*(const __half2*)&hep[gi]);
                    const float2 x2 = __half22float2(*(const __half2*)&hex[gi]);
                    const float r0 = g0 * e2.x + (1.f - g0) * x2.x;
                    const float r1 = g1 * e2.y + (1.f - g1) * x2.y;
                    *(__half2*)&Ch[gi] = __floats2half2_rn(r0, r1);
                } else if constexpr (MODE == 4) {
                    v0 += bias[gc]; v1 += bias[gc + 1];
                    *(__half2*)&Ch[gi] = __floats2half2_rn(v0, v1);
                } else {  // MODE 5
                    if (gc < 2 * DIN) {
                        v0 = fmaxf(v0, 0.f) + 1e-4f;
                        v1 = fmaxf(v1, 0.f) + 1e-4f;
                    }
                    *(__half2*)&Ch[gi] = __floats2half2_rn(v0, v1);
                }
            }
        }
    }
}

// ---------------- fp32 -> half copy ----------------------------------------------
__global__ void half_copy(const float4* __restrict__ s, __half2* __restrict__ d)
{
    const int i = blockIdx.x * 256 + threadIdx.x;
    float4 v = s[i];
    d[2 * i]     = __floats2half2_rn(v.x, v.y);
    d[2 * i + 1] = __floats2half2_rn(v.z, v.w);
}

// ---------------- transpose + convert: WT[n][k] = half(W[k][n]) -------------------
__global__ void transpose_half(const float* __restrict__ S, __half* __restrict__ D,
                               int K, int N)
{
    __shared__ float t[32][33];
    const int bn = blockIdx.x * 32, bk = blockIdx.y * 32;
    const int tx = threadIdx.x, ty = threadIdx.y;
#pragma unroll
    for (int i = 0; i < 32; i += 8)
        t[ty + i][tx] = S[(size_t)(bk + ty + i) * N + bn + tx];
    __syncthreads();
#pragma unroll
    for (int i = 0; i < 32; i += 8)
        D[(size_t)(bn + ty + i) * K + bk + tx] = __float2half_rn(t[tx][ty + i]);
}

// fused 3-way transpose for Wq/Wk/Wv
__global__ void transpose_qkv(const float* __restrict__ Wq, const float* __restrict__ Wk,
                              const float* __restrict__ Wv, __half* __restrict__ D)
{
    __shared__ float t[32][33];
    const float* S = (blockIdx.z == 0) ? Wq : (blockIdx.z == 1) ? Wk : Wv;
    __half* Dz = D + (size_t)blockIdx.z * DIN * DIN;
    const int bn = blockIdx.x * 32, bk = blockIdx.y * 32;
    const int tx = threadIdx.x, ty = threadIdx.y;
#pragma unroll
    for (int i = 0; i < 32; i += 8)
        t[ty + i][tx] = S[(size_t)(bk + ty + i) * DIN + bn + tx];
    __syncthreads();
#pragma unroll
    for (int i = 0; i < 32; i += 8)
        Dz[(size_t)(bn + ty + i) * DIN + bk + tx] = __float2half_rn(t[tx][ty + i]);
}

// ---------------- kv via HMMA: kvpart[chunk][h][e][d] = sum_b v[b][e]*k[b][d] ------
#define KVRS 136
__global__ void __launch_bounds__(256) kv_mma(const __half* __restrict__ qkv)
{
    __shared__ __half ksm[2][16 * KVRS];
    __shared__ __half vsm[2][16 * KVRS];
    __shared__ float ksum_s[256];

    const int h = blockIdx.x;
    const int chunk = blockIdx.y;
    const int b0 = chunk * (BATCH / KV_SPLIT);   // 512 rows
    const int tid = threadIdx.x;
    const int wid = tid >> 5, lane = tid & 31;
    const int wm = (wid >> 2) * 64;
    const int wn = (wid & 3) * 32;

    const __half* kbase = qkv + 2048 + h * DHEAD;
    const __half* vbase = qkv + 4096 + h * DHEAD;
    const uint32_t ksu = smem_u32(&ksm[0][0]);
    const uint32_t vsu = smem_u32(&vsm[0][0]);

    const uint32_t a_lane = (uint32_t)((((lane & 7) + ((lane >> 4) & 1) * 8) * KVRS
                                        + ((lane >> 3) & 1) * 8) * 2);
    const uint32_t b_lane = (uint32_t)((((lane & 7) + ((lane >> 3) & 1) * 8) * KVRS
                                        + ((lane >> 4) & 1) * 8) * 2);

    auto load = [&](int buf, int bb) {
        const int r = tid >> 4, g = tid & 15;
        const size_t row = (size_t)(b0 + bb + r) * NQKV;
        cp16(ksu + (uint32_t)(buf * 16 * KVRS + r * KVRS + g * 8) * 2u, kbase + row + g * 8);
        cp16(vsu + (uint32_t)(buf * 16 * KVRS + r * KVRS + g * 8) * 2u, vbase + row + g * 8);
    };

    float acc[4][4][4];
#pragma unroll
    for (int mt = 0; mt < 4; mt++)
#pragma unroll
        for (int nt = 0; nt < 4; nt++)
#pragma unroll
            for (int e = 0; e < 4; e++) acc[mt][nt][e] = 0.0f;
    float ksacc = 0.0f;
    const int kcol = tid & 127;
    const int krb  = (tid >> 7) * 8;

    load(0, 0);
    CP_COMMIT();

    for (int it = 0; it < (BATCH / KV_SPLIT) / 16; it++) {   // 32 iters
        const int buf = it & 1;
        if (it + 1 < (BATCH / KV_SPLIT) / 16) load(buf ^ 1, (it + 1) * 16);
        CP_COMMIT();
        CP_WAIT(1);
        __syncthreads();

        const uint32_t kb = ksu + (uint32_t)(buf * 16 * KVRS) * 2u;
        const uint32_t vb = vsu + (uint32_t)(buf * 16 * KVRS) * 2u;

        uint32_t a[4][4], b[4][2];
#pragma unroll
        for (int mt = 0; mt < 4; mt++)
            LDSM_X4_T(a[mt][0], a[mt][1], a[mt][2], a[mt][3],
                      vb + a_lane + (uint32_t)((wm + mt * 16) * 2));
#pragma unroll
        for (int p = 0; p < 2; p++)
            LDSM_X4_T(b[2 * p][0], b[2 * p][1], b[2 * p + 1][0], b[2 * p + 1][1],
                      kb + b_lane + (uint32_t)((wn + p * 16) * 2));
#pragma unroll
        for (int mt = 0; mt < 4; mt++)
#pragma unroll
            for (int nt = 0; nt < 4; nt++)
                MMA_F16(acc[mt][nt], a[mt], b[nt]);

        const __half* kcolp = &ksm[buf][krb * KVRS + kcol];
#pragma unroll
        for (int r = 0; r < 8; r++) ksacc += __half2float(kcolp[r * KVRS]);
        __syncthreads();
    }

    float* dst = g_kvpart + (size_t)chunk * (HEADS * DHEAD * DHEAD) + h * DHEAD * DHEAD;
    const int lr = lane >> 2, lc = lane & 3;
#pragma unroll
    for (int mt = 0; mt < 4; mt++)
#pragma unroll
        for (int nt = 0; nt < 4; nt++)
#pragma unroll
            for (int hh = 0; hh < 2; hh++) {
                const int e = wm + mt * 16 + lr + hh * 8;
                const int d = wn + nt * 8 + 2 * lc;
                *(float2*)&dst[e * DHEAD + d] =
                    make_float2(acc[mt][nt][hh * 2 + 0], acc[mt][nt][hh * 2 + 1]);
            }

    ksum_s[tid] = ksacc;
    __syncthreads();
    if (tid < 128)
        g_ksumpart[chunk * DIN + h * DHEAD + tid] = ksum_s[tid] + ksum_s[tid + 128];
}

// ---------------- final reductions: kvT (half) + ksum (fp32) -----------------------
__global__ void kv_final()
{
    int i = blockIdx.x * 256 + threadIdx.x;
    float s = 0.0f;
    for (int c = 0; c < KV_SPLIT; c++) s += g_kvpart[(size_t)c * (HEADS * DHEAD * DHEAD) + i];
    g_kvT[i] = __float2half_rn(s);
    if (i < DIN) {
        float t = 0.0f;
        for (int c = 0; c < KV_SPLIT; c++) t += g_ksumpart[c * DIN + i];
        g_ksum[i] = t;
    }
}

// ---------------- attention via HMMA: att = (q @ kvT^T) * z ------------------------
#define ATT_SMEM (2 * 128 * 72 * 2 * 2 + 1024)
__global__ void __launch_bounds__(256) attn_mma(const __half* __restrict__ qkv,
                                                __half* __restrict__ att)
{
    extern __shared__ char smc[];
    __half* As = (__half*)smc;
    __half* Bs = (__half*)(smc + 2 * 128 * 72 * 2);
    float* ksum_s = (float*)(smc + 4 * 128 * 72 * 2);
    float* z_s    = ksum_s + 128;

    const int h  = blockIdx.y;
    const int b0 = blockIdx.x * 128;
    const int tid = threadIdx.x;
    const int wid = tid >> 5, lane = tid & 31;
    const int wm = (wid >> 2) * 64, wn = (wid & 3) * 32;
    const uint32_t asu = smem_u32(As), bsu = smem_u32(Bs);

    const __half* qb  = qkv + h * DHEAD;
    const __half* kvb = g_kvT + (size_t)h * DHEAD * DHEAD;

#pragma unroll
    for (int kt = 0; kt < 2; kt++) {
#pragma unroll
        for (int i = 0; i < 4; i++) {
            int idx = tid + i * 256;
            int r = idx >> 3, g = idx & 7;
            cp16(asu + (uint32_t)(kt * 128 * 72 + r * 72 + g * 8) * 2u,
                 qb + (size_t)(b0 + r) * NQKV + kt * 64 + g * 8);
            cp16(bsu + (uint32_t)(kt * 128 * 72 + r * 72 + g * 8) * 2u,
                 kvb + r * DHEAD + kt * 64 + g * 8);
        }
    }
    CP_COMMIT();
    if (tid < 128) ksum_s[tid] = g_ksum[h * DHEAD + tid];
    CP_WAIT(0);
    __syncthreads();

    {
        int r = tid >> 1, hf = tid & 1;
        const __half* qrow = As + hf * 128 * 72 + r * 72;
        float s = 0.0f;
        for (int d = 0; d < 64; d++) s += __half2float(qrow[d]) * ksum_s[hf * 64 + d];
        s += __shfl_xor_sync(0xffffffffu, s, 1);
        if (hf == 0) z_s[r] = 1.0f / (s + 1e-6f);
    }
    __syncthreads();

    const uint32_t a_lane = (uint32_t)(((lane & 15) * 72 + (lane >> 4) * 8) * 2);
    const uint32_t b_lane = (uint32_t)(((((lane >> 4) << 3) + (lane & 7)) * 72
                                        + ((lane >> 3) & 1) * 8) * 2);

    float acc[4][4][4];
#pragma unroll
    for (int mt = 0; mt < 4; mt++)
#pragma unroll
        for (int nt = 0; nt < 4; nt++)
#pragma unroll
            for (int e = 0; e < 4; e++) acc[mt][nt][e] = 0.0f;

#pragma unroll
    for (int kt = 0; kt < 2; kt++) {
        const uint32_t abase = asu + (uint32_t)(kt * 128 * 72 + wm * 72) * 2u + a_lane;
        const uint32_t bbase = bsu + (uint32_t)(kt * 128 * 72 + wn * 72) * 2u + b_lane;
#pragma unroll
        for (int kc = 0; kc < 4; kc++) {
            uint32_t a[4][4], b[4][2];
            const uint32_t ko = (uint32_t)(kc * 32);
#pragma unroll
            for (int mt = 0; mt < 4; mt++)
                LDSM_X4(a[mt][0], a[mt][1], a[mt][2], a[mt][3],
                        abase + (uint32_t)(mt * 16 * 72 * 2) + ko);
#pragma unroll
            for (int p = 0; p < 2; p++)
                LDSM_X4(b[2 * p][0], b[2 * p][1], b[2 * p + 1][0], b[2 * p + 1][1],
                        bbase + (uint32_t)(p * 16 * 72 * 2) + ko);
#pragma unroll
            for (int mt = 0; mt < 4; mt++)
#pragma unroll
                for (int nt = 0; nt < 4; nt++)
                    MMA_F16(acc[mt][nt], a[mt], b[nt]);
        }
    }

    const int lr = lane >> 2, lc = lane & 3;
#pragma unroll
    for (int mt = 0; mt < 4; mt++) {
#pragma unroll
        for (int nt = 0; nt < 4; nt++) {
#pragma unroll
            for (int hh = 0; hh < 2; hh++) {
                const int rl = wm + mt * 16 + lr + hh * 8;
                const int gc = wn + nt * 8 + 2 * lc;
                const float z = z_s[rl];
                const float v0 = acc[mt][nt][hh * 2 + 0] * z;
                const float v1 = acc[mt][nt][hh * 2 + 1] * z;
                *(__half2*)&att[(size_t)(b0 + rl) * DIN + h * DHEAD + gc] =
                    __floats2half2_rn(v0, v1);
            }
        }
    }
}

// ---------------- launch -----------------------------------------------------------
extern "C" void kernel_launch(void* const* d_in, const int* in_sizes, int n_in,
                              void* d_out, int out_size)
{
    const float* x    = (const float*)d_in[0];
    const float* Wq   = (const float*)d_in[1];
    const float* Wk   = (const float*)d_in[2];
    const float* Wv   = (const float*)d_in[3];
    const float* Wo   = (const float*)d_in[4];
    const float* bo   = (const float*)d_in[5];
    const float* Wg   = (const float*)d_in[6];
    const float* bg   = (const float*)d_in[7];
    const float* Wout = (const float*)d_in[8];
    const float* bout = (const float*)d_in[9];
    float* out = (float*)d_out;

    __half *xh_, *qkvh_, *att_, *opr_, *gt_;
    __half *wqkvT_, *woT_, *wgT_, *woutT_;
    cudaGetSymbolAddress((void**)&xh_,    g_xh);
    cudaGetSymbolAddress((void**)&qkvh_,  g_qkvh);
    cudaGetSymbolAddress((void**)&att_,   g_att);
    cudaGetSymbolAddress((void**)&opr_,   g_opr);
    cudaGetSymbolAddress((void**)&gt_,    g_gt);
    cudaGetSymbolAddress((void**)&wqkvT_, g_wqkvT);
    cudaGetSymbolAddress((void**)&woT_,   g_woT);
    cudaGetSymbolAddress((void**)&wgT_,   g_wgT);
    cudaGetSymbolAddress((void**)&woutT_, g_woutT);

    cudaFuncSetAttribute(gemm_h<2>, cudaFuncAttributeMaxDynamicSharedMemorySize, GEMM_SMEM);
    cudaFuncSetAttribute(gemm_h<3>, cudaFuncAttributeMaxDynamicSharedMemorySize, GEMM_SMEM);
    cudaFuncSetAttribute(gemm_h<4>, cudaFuncAttributeMaxDynamicSharedMemorySize, GEMM_SMEM);
    cudaFuncSetAttribute(gemm_h<5>, cudaFuncAttributeMaxDynamicSharedMemorySize, GEMM_SMEM);
    cudaFuncSetAttribute(attn_mma, cudaFuncAttributeMaxDynamicSharedMemorySize, ATT_SMEM);

    const dim3 blk(256);
    const dim3 tblk(32, 8);

    // idx 0-2: prep; idx 3 = QKV GEMM (ncu lands here)
    half_copy<<<(BATCH * DIN) / 1024, 256>>>((const float4*)x, (__half2*)xh_);        // 0
    transpose_qkv<<<dim3(DIN / 32, DIN / 32, 3), tblk>>>(Wq, Wk, Wv, wqkvT_);         // 1
    transpose_half<<<dim3(DIN / 32, DIN / 32), tblk>>>(Wo, woT_, DIN, DIN);           // 2

    // 3: fused QKV GEMM -> half qkv, relu-feature on q,k columns
    gemm_h<5><<<dim3(NQKV / BN, BATCH / BM), blk, GEMM_SMEM>>>(
        xh_, xh_, DIN, DIN / BK, wqkvT_, DIN,
        nullptr, nullptr, nullptr, nullptr, qkvh_, NQKV);

    transpose_half<<<dim3(DIN / 32, (2 * DIN) / 32), tblk>>>(Wg, wgT_, 2 * DIN, DIN); // 4
    transpose_half<<<dim3(DOUT / 32, DIN / 32), tblk>>>(Wout, woutT_, DIN, DOUT);     // 5

    // kv + ksum partials via HMMA, then final reduce -> half kvT + fp32 ksum
    kv_mma<<<dim3(HEADS, KV_SPLIT), 256>>>(qkvh_);
    kv_final<<<dim3((HEADS * DHEAD * DHEAD) / 256), 256>>>();

    // attention via HMMA
    attn_mma<<<dim3(BATCH / 128, HEADS), 256, ATT_SMEM>>>(qkvh_, att_);

    // out_proj = att @ Wo + bo -> half opr
    gemm_h<4><<<dim3(DIN / BN, BATCH / BM), blk, GEMM_SMEM>>>(
        att_, att_, DIN, DIN / BK, woT_, DIN,
        bo, nullptr, nullptr, nullptr, opr_, DIN);

    // gate GEMM over concat [opr | xh]; blend half opr / xh -> half gt
    gemm_h<3><<<dim3(DIN / BN, BATCH / BM), blk, GEMM_SMEM>>>(
        opr_, xh_, DIN, (2 * DIN) / BK, wgT_, 2 * DIN,
        bg, opr_, xh_, nullptr, gt_, DIN);

    // out = gt @ Wout + bout (fp32)
    gemm_h<2><<<dim3(DOUT / BN, BATCH / BM), blk, GEMM_SMEM>>>(
        gt_, gt_, DIN, DIN / BK, woutT_, DIN,
        bout, nullptr, nullptr, out, nullptr, DOUT);
}